// round 10
// baseline (speedup 1.0000x reference)
#include <cuda_runtime.h>
#include <cstdint>
#include <cstddef>

using ull = unsigned long long;

#define NROWS   16                     // rows per CTA
#define THREADS 128
// x row stride: 64*D + 4 floats  (== 4 mod 32: warp rows spread bank quads)
#define XS_BUF  5184                   // floats: 16 * (64*5+4) worst case (l=2)
#define WS_BUF  1280                   // floats: 64 w-rows * 20 (padded, permuted)
#define SMEM_FLOATS (2*XS_BUF + 2*WS_BUF)
#define SMEM_BYTES  (SMEM_FLOATS * 4)  // 51712 B -> 4 CTAs/SM

__device__ __forceinline__ void cpa16(float* dst, const float* src) {
    unsigned d = (unsigned)__cvta_generic_to_shared(dst);
    asm volatile("cp.async.cg.shared.global [%0], [%1], 16;" :: "r"(d), "l"(src));
}
__device__ __forceinline__ ull pack2(float a) {
    ull r; asm("mov.b64 %0, {%1, %1};" : "=l"(r) : "f"(a)); return r;
}
__device__ __forceinline__ void ffma2(ull& acc, ull a, ull b) {
    asm("fma.rn.f32x2 %0, %1, %2, %0;" : "+l"(acc) : "l"(a), "l"(b));
}
__device__ __forceinline__ ull addf2(ull a, ull b) {
    ull r; asm("add.rn.f32x2 %0, %1, %2;" : "=l"(r) : "l"(a), "l"(b)); return r;
}

// w smem row permutation (verified): mi = kg*16 + uh*8 + ul ->
// pm = ul*8 + res, res = ((kg>>1)<<2) | (uh<<1) | (kg&1), row stride 20 floats.
// The 8 (kg,og) read addresses pm*20 + og*8 hit all 8 bank quads.
__device__ __forceinline__ int w_res(int kg, int uh) {
    return ((kg >> 1) << 2) | (uh << 1) | (kg & 1);
}

// Stage one (l, c) chunk.
template<int D>
__device__ __forceinline__ void stage_chunk(const float* __restrict__ x,
                                            const float* __restrict__ wl,
                                            int n0, int c, int off,
                                            float* xs, float* ws, int tid)
{
    const int stride = 64 * D + 4;
    const int row = tid >> 3, l8 = tid & 7;   // 16 rows, 8 threads/row
    const float* gr = x + (size_t)(n0 + row) * 9216 + c * 576 + off;
    float* sr = xs + row * stride;
    // 16*D float4 per row, 8 threads/row -> 2*D vec4 each; dense dest
#pragma unroll
    for (int k = 0; k < 2 * D; k++) {
        int v4 = (l8 + 8 * k) * 4;
        cpa16(sr + v4, gr + v4);
    }
    // weights: 256 float4 staged by 128 threads -> 2 each; permuted destination
    const int m = tid >> 1;                   // mi 0..63
    const int kg = m >> 4, uh = (m >> 3) & 1, ul = m & 7;
    const int pm = ul * 8 + w_res(kg, uh);
#pragma unroll
    for (int j = 0; j < 2; j++) {
        int q = (tid & 1) * 2 + j;            // float4 index within 16 floats
        cpa16(ws + pm * 20 + q * 4, wl + c * 1024 + m * 16 + q * 4);
    }
    asm volatile("cp.async.commit_group;" ::: "memory");
}

// Compute one chunk. D = irrep dim (1/3/5), DOFF = dim offset in acc (0/1/4).
// Thread (r, kg, og) owns mi in [kg*16, kg*16+16), outputs [og*8, og*8+8).
template<int D, int DOFF>
__device__ __forceinline__ void compute_chunk(const float* __restrict__ xs,
                                              const float* __restrict__ ws,
                                              ull (&acc)[4][9],
                                              int r, int kg, int og)
{
    const float* xr = xs + r * (64 * D + 4) + kg * (16 * D);
    const float* wbase = ws + og * 8;
#pragma unroll
    for (int b = 0; b < 4; b++) {                    // blocks of 4 multiplicities
        float xh[4 * D];
        const float4* xp = (const float4*)(xr + b * 4 * D);
#pragma unroll
        for (int v = 0; v < D; v++) {
            float4 t = xp[v];
            xh[4*v] = t.x; xh[4*v+1] = t.y; xh[4*v+2] = t.z; xh[4*v+3] = t.w;
        }
#pragma unroll
        for (int u4 = 0; u4 < 4; u4++) {
            const int u = b * 4 + u4;                // local mi 0..15
            const int uh = u >> 3, ul = u & 7;
            const int pm = ul * 8 + w_res(kg, uh);
            const ulonglong2* wp = (const ulonglong2*)(wbase + pm * 20);
            ulonglong2 w01 = wp[0], w23 = wp[1];     // 2x LDS.128, broadcast-friendly
            ull w4r[4] = { w01.x, w01.y, w23.x, w23.y };
#pragma unroll
            for (int d = 0; d < D; d++) {
                ull av = pack2(xh[u4 * D + d]);      // 1 pack feeds 4 FFMA2
#pragma unroll
                for (int p = 0; p < 4; p++)
                    ffma2(acc[p][DOFF + d], av, w4r[p]);
            }
        }
    }
}

__global__ void __launch_bounds__(THREADS, 4)
GeneralLinear_841813590622_kernel(const float* __restrict__ x,
                                  const float* __restrict__ w0,
                                  const float* __restrict__ w1,
                                  const float* __restrict__ w2,
                                  float* __restrict__ out)
{
    extern __shared__ float smem[];
    float* xsb[2] = { smem, smem + XS_BUF };
    float* wsb[2] = { smem + 2 * XS_BUF, smem + 2 * XS_BUF + WS_BUF };
    const float* wl[3] = { w0, w1, w2 };

    const int tid = threadIdx.x;
    const int n0 = blockIdx.x * NROWS;
    const int r = tid >> 3, kg = (tid >> 1) & 3, og = tid & 1;

    ull acc[4][9];
#pragma unroll
    for (int p = 0; p < 4; p++)
#pragma unroll
        for (int q = 0; q < 9; q++) acc[p][q] = 0ull;

    stage_chunk<1>(x, wl[0], n0, 0, 0, xsb[0], wsb[0], tid);

    for (int i = 0; i < 48; i++) {
        const int b = i & 1;
        const int nx = i + 1;
        if (nx < 48) {
            const int ln = nx >> 4, cn = nx & 15;
            float* xsn = xsb[nx & 1];
            float* wsn = wsb[nx & 1];
            if (ln == 0)      stage_chunk<1>(x, wl[0], n0, cn, 0,   xsn, wsn, tid);
            else if (ln == 1) stage_chunk<3>(x, wl[1], n0, cn, 64,  xsn, wsn, tid);
            else              stage_chunk<5>(x, wl[2], n0, cn, 256, xsn, wsn, tid);
            asm volatile("cp.async.wait_group 1;" ::: "memory");
        } else {
            asm volatile("cp.async.wait_group 0;" ::: "memory");
        }
        __syncthreads();

        const int l = i >> 4;
        if (l == 0)      compute_chunk<1, 0>(xsb[b], wsb[b], acc, r, kg, og);
        else if (l == 1) compute_chunk<3, 1>(xsb[b], wsb[b], acc, r, kg, og);
        else             compute_chunk<5, 4>(xsb[b], wsb[b], acc, r, kg, og);
        __syncthreads();   // protect buffer b before restaging
    }

    // ---- reduce over kg (lane bits 1..2) via 64-bit butterfly shuffles ----
#pragma unroll
    for (int mask = 2; mask <= 4; mask <<= 1) {
#pragma unroll
        for (int p = 0; p < 4; p++)
#pragma unroll
            for (int q = 0; q < 9; q++) {
                ull o = __shfl_xor_sync(0xffffffffu, acc[p][q], mask);
                acc[p][q] = addf2(acc[p][q], o);
            }
    }

    // ---- kg==0 threads stage their (row, og-half) 72 floats to smem (scaled) ----
    const float s = 0.03125f;   // 1/sqrt(1024)
    float* sred = xsb[0];       // free after final sync
    if ((tid & 6) == 0) {       // kg == 0
#pragma unroll
        for (int p = 0; p < 4; p++)
#pragma unroll
            for (int q = 0; q < 9; q++) {
                float lo, hi;
                asm("mov.b64 {%0, %1}, %2;" : "=f"(lo), "=f"(hi) : "l"(acc[p][q]));
                sred[r * 144 + (og * 8 + 2 * p) * 9 + q]     = lo * s;
                sred[r * 144 + (og * 8 + 2 * p + 1) * 9 + q] = hi * s;
            }
    }
    __syncthreads();

    // ---- cooperative coalesced float4 store: 16 rows * 144 floats = 576 float4 ----
    const float4* s4 = (const float4*)sred;
    float4* o4 = (float4*)(out + (size_t)n0 * 144);
#pragma unroll
    for (int k = 0; k < 5; k++) {
        int idx = tid + THREADS * k;
        if (idx < 576) o4[idx] = s4[idx];
    }
}

extern "C" void kernel_launch(void* const* d_in, const int* in_sizes, int n_in,
                              void* d_out, int out_size)
{
    const float* x  = (const float*)d_in[0];
    const float* w0 = (const float*)d_in[1];
    const float* w1 = (const float*)d_in[2];
    const float* w2 = (const float*)d_in[3];
    float* out = (float*)d_out;

    cudaFuncSetAttribute(GeneralLinear_841813590622_kernel,
                         cudaFuncAttributeMaxDynamicSharedMemorySize, SMEM_BYTES);
    GeneralLinear_841813590622_kernel<<<512, THREADS, SMEM_BYTES>>>(x, w0, w1, w2, out);
}

// round 11
// speedup vs baseline: 1.2143x; 1.2143x over previous
#include <cuda_runtime.h>
#include <cstdint>
#include <cstddef>

using ull = unsigned long long;

#define NROWS   16                     // rows per CTA
#define THREADS 128
// x row stride: 64*D + 4 floats  (== 4 mod 32: warp rows spread bank quads)
#define XS_BUF  5184                   // floats: 16 * (64*5+4) worst case (l=2)
#define WS_BUF  1280                   // floats: 64 w-rows * 20 (padded, permuted)
#define SLOT_FLOATS (XS_BUF + WS_BUF)  // 6464
#define NSLOTS  4
#define SMEM_BYTES (NSLOTS * SLOT_FLOATS * 4)   // 103424 B -> 2 CTAs/SM

__device__ __forceinline__ void cpa16(float* dst, const float* src) {
    unsigned d = (unsigned)__cvta_generic_to_shared(dst);
    asm volatile("cp.async.cg.shared.global [%0], [%1], 16;" :: "r"(d), "l"(src));
}
__device__ __forceinline__ ull pack2(float a) {
    ull r; asm("mov.b64 %0, {%1, %1};" : "=l"(r) : "f"(a)); return r;
}
__device__ __forceinline__ void ffma2(ull& acc, ull a, ull b) {
    asm("fma.rn.f32x2 %0, %1, %2, %0;" : "+l"(acc) : "l"(a), "l"(b));
}
__device__ __forceinline__ ull addf2(ull a, ull b) {
    ull r; asm("add.rn.f32x2 %0, %1, %2;" : "=l"(r) : "l"(a), "l"(b)); return r;
}

// w smem row permutation (verified): mi = kg*16 + uh*8 + ul ->
// pm = ul*8 + res, res = ((kg>>1)<<2) | (uh<<1) | (kg&1), row stride 20 floats.
// The 8 (kg,og) read addresses pm*20 + og*8 hit all 8 bank quads.
__device__ __forceinline__ int w_res(int kg, int uh) {
    return ((kg >> 1) << 2) | (uh << 1) | (kg & 1);
}

// Stage one (l, c) chunk into a ring slot; commits one cp.async group.
template<int D>
__device__ __forceinline__ void stage_chunk(const float* __restrict__ x,
                                            const float* __restrict__ wl,
                                            int n0, int c, int off,
                                            float* xs, float* ws, int tid)
{
    const int stride = 64 * D + 4;
    const int row = tid >> 3, l8 = tid & 7;   // 16 rows, 8 threads/row
    const float* gr = x + (size_t)(n0 + row) * 9216 + c * 576 + off;
    float* sr = xs + row * stride;
    // 16*D float4 per row, 8 threads/row -> 2*D vec4 each; dense dest
#pragma unroll
    for (int k = 0; k < 2 * D; k++) {
        int v4 = (l8 + 8 * k) * 4;
        cpa16(sr + v4, gr + v4);
    }
    // weights: 256 float4 staged by 128 threads -> 2 each; permuted destination
    const int m = tid >> 1;                   // mi 0..63
    const int kg = m >> 4, uh = (m >> 3) & 1, ul = m & 7;
    const int pm = ul * 8 + w_res(kg, uh);
#pragma unroll
    for (int j = 0; j < 2; j++) {
        int q = (tid & 1) * 2 + j;            // float4 index within 16 floats
        cpa16(ws + pm * 20 + q * 4, wl + c * 1024 + m * 16 + q * 4);
    }
    asm volatile("cp.async.commit_group;" ::: "memory");
}

// Compute one chunk. D = irrep dim (1/3/5), DOFF = dim offset in acc (0/1/4).
// Thread (r, kg, og) owns mi in [kg*16, kg*16+16), outputs [og*8, og*8+8).
template<int D, int DOFF>
__device__ __forceinline__ void compute_chunk(const float* __restrict__ xs,
                                              const float* __restrict__ ws,
                                              ull (&acc)[4][9],
                                              int r, int kg, int og)
{
    const float* xr = xs + r * (64 * D + 4) + kg * (16 * D);
    const float* wbase = ws + og * 8;
#pragma unroll
    for (int b = 0; b < 4; b++) {                    // blocks of 4 multiplicities
        float xh[4 * D];
        const float4* xp = (const float4*)(xr + b * 4 * D);
#pragma unroll
        for (int v = 0; v < D; v++) {
            float4 t = xp[v];
            xh[4*v] = t.x; xh[4*v+1] = t.y; xh[4*v+2] = t.z; xh[4*v+3] = t.w;
        }
#pragma unroll
        for (int u4 = 0; u4 < 4; u4++) {
            const int u = b * 4 + u4;                // local mi 0..15
            const int uh = u >> 3, ul = u & 7;
            const int pm = ul * 8 + w_res(kg, uh);
            const ulonglong2* wp = (const ulonglong2*)(wbase + pm * 20);
            ulonglong2 w01 = wp[0], w23 = wp[1];     // 2x LDS.128, broadcast
            ull w4r[4] = { w01.x, w01.y, w23.x, w23.y };
#pragma unroll
            for (int d = 0; d < D; d++) {
                ull av = pack2(xh[u4 * D + d]);      // 1 pack feeds 4 FFMA2
#pragma unroll
                for (int p = 0; p < 4; p++)
                    ffma2(acc[p][DOFF + d], av, w4r[p]);
            }
        }
    }
}

__global__ void __launch_bounds__(THREADS, 2)
GeneralLinear_841813590622_kernel(const float* __restrict__ x,
                                  const float* __restrict__ w0,
                                  const float* __restrict__ w1,
                                  const float* __restrict__ w2,
                                  float* __restrict__ out)
{
    extern __shared__ float smem[];
    const float* wl[3] = { w0, w1, w2 };

    const int tid = threadIdx.x;
    const int n0 = blockIdx.x * NROWS;
    const int r = tid >> 3, kg = (tid >> 1) & 3, og = tid & 1;

    ull acc[4][9];
#pragma unroll
    for (int p = 0; p < 4; p++)
#pragma unroll
        for (int q = 0; q < 9; q++) acc[p][q] = 0ull;

    // prologue: stage chunks 0 and 1 (both l=0) into slots 0 and 1
    stage_chunk<1>(x, w0, n0, 0, 0, smem,               smem + XS_BUF,               tid);
    stage_chunk<1>(x, w0, n0, 1, 0, smem + SLOT_FLOATS, smem + SLOT_FLOATS + XS_BUF, tid);

    for (int i = 0; i < 48; i++) {
        // stage chunk i+2 (slot reuse safe: compute of chunk i-2 finished
        // before the previous iteration's __syncthreads)
        const int nx = i + 2;
        if (nx < 48) {
            const int ln = nx >> 4, cn = nx & 15;
            float* xsn = smem + (size_t)(nx & 3) * SLOT_FLOATS;
            float* wsn = xsn + XS_BUF;
            if (ln == 0)      stage_chunk<1>(x, wl[0], n0, cn, 0,   xsn, wsn, tid);
            else if (ln == 1) stage_chunk<3>(x, wl[1], n0, cn, 64,  xsn, wsn, tid);
            else              stage_chunk<5>(x, wl[2], n0, cn, 256, xsn, wsn, tid);
        } else {
            asm volatile("cp.async.commit_group;" ::: "memory");  // keep group count
        }
        asm volatile("cp.async.wait_group 2;" ::: "memory");      // chunk i landed (mine)
        __syncthreads();                                          // ...and everyone's

        float* xsb = smem + (size_t)(i & 3) * SLOT_FLOATS;
        float* wsb = xsb + XS_BUF;
        const int l = i >> 4;
        if (l == 0)      compute_chunk<1, 0>(xsb, wsb, acc, r, kg, og);
        else if (l == 1) compute_chunk<3, 1>(xsb, wsb, acc, r, kg, og);
        else             compute_chunk<5, 4>(xsb, wsb, acc, r, kg, og);
    }

    // ---- reduce over kg (lane bits 1..2) via 64-bit butterfly shuffles ----
#pragma unroll
    for (int mask = 2; mask <= 4; mask <<= 1) {
#pragma unroll
        for (int p = 0; p < 4; p++)
#pragma unroll
            for (int q = 0; q < 9; q++) {
                ull o = __shfl_xor_sync(0xffffffffu, acc[p][q], mask);
                acc[p][q] = addf2(acc[p][q], o);
            }
    }

    // ---- kg==0 threads stage their (row, og-half) 72 floats to smem (scaled) ----
    // slot 0 x-region is free: its last chunk (44) finished >=3 syncs ago.
    const float s = 0.03125f;   // 1/sqrt(1024)
    float* sred = smem;
    if ((tid & 6) == 0) {       // kg == 0
#pragma unroll
        for (int p = 0; p < 4; p++)
#pragma unroll
            for (int q = 0; q < 9; q++) {
                float lo, hi;
                asm("mov.b64 {%0, %1}, %2;" : "=f"(lo), "=f"(hi) : "l"(acc[p][q]));
                sred[r * 144 + (og * 8 + 2 * p) * 9 + q]     = lo * s;
                sred[r * 144 + (og * 8 + 2 * p + 1) * 9 + q] = hi * s;
            }
    }
    __syncthreads();

    // ---- cooperative coalesced float4 store: 16 rows * 144 floats = 576 float4 ----
    const float4* s4 = (const float4*)sred;
    float4* o4 = (float4*)(out + (size_t)n0 * 144);
#pragma unroll
    for (int k = 0; k < 5; k++) {
        int idx = tid + THREADS * k;
        if (idx < 576) o4[idx] = s4[idx];
    }
}

extern "C" void kernel_launch(void* const* d_in, const int* in_sizes, int n_in,
                              void* d_out, int out_size)
{
    const float* x  = (const float*)d_in[0];
    const float* w0 = (const float*)d_in[1];
    const float* w1 = (const float*)d_in[2];
    const float* w2 = (const float*)d_in[3];
    float* out = (float*)d_out;

    cudaFuncSetAttribute(GeneralLinear_841813590622_kernel,
                         cudaFuncAttributeMaxDynamicSharedMemorySize, SMEM_BYTES);
    GeneralLinear_841813590622_kernel<<<512, THREADS, SMEM_BYTES>>>(x, w0, w1, w2, out);
}